// round 3
// baseline (speedup 1.0000x reference)
#include <cuda_runtime.h>
#include <math.h>

#define BB 32
#define CC 256
#define DD 128
#define NN 1024
#define EPS 1e-5f
#define SCALE 0.08838834764831843f  // 1/sqrt(128)

// ---------------- scratch (device globals; no allocations allowed) ----------
__device__ float g_q[2][BB * NN * DD];       // (dir, b, n, d)   16.8MB x2
__device__ float g_k[2][BB * NN * DD];
__device__ float g_v[2][BB * NN * CC];       // (dir, b, n, c)   33.5MB x2
__device__ float g_o[2][BB * NN * CC];       // attention output (b, n, c)
__device__ float g_p[2ll * BB * NN * NN];    // logits/probs     268MB
__device__ float g_red[64 * 2];              // per (dir,b): mean, rstd

// ---------------- common GEMM tile config ------------------------------------
// BM=BN=128, BK=8, 256 threads, each thread computes (4+4)x(4+4) split tile
#define PAD 132

// =============================================================================
// proj: Y[b,n,d] = sum_c X[b,c,n] * W[d,c]
// which: 0 -> g_q[dir] (Dout=128), 1 -> g_k[dir] (128), 2 -> g_v[dir] (256)
// =============================================================================
__global__ __launch_bounds__(256)
void proj_kernel(const float* __restrict__ X, const float* __restrict__ W,
                 int dir, int which) {
    float* Y;
    int Dout;
    if (which == 0)      { Y = g_q[dir]; Dout = DD; }
    else if (which == 1) { Y = g_k[dir]; Dout = DD; }
    else                 { Y = g_v[dir]; Dout = CC; }

    const int b  = blockIdx.z;
    const int n0 = blockIdx.x * 128;
    const int d0 = blockIdx.y * 128;
    const float* Xb = X + (size_t)b * CC * NN;
    float* Yb = Y + (size_t)b * NN * Dout;

    __shared__ float As[8][PAD];
    __shared__ float Bs[8][PAD];
    float acc[8][8] = {};
    const int t  = threadIdx.x;
    const int tx = t & 15, ty = t >> 4;

    for (int c0 = 0; c0 < CC; c0 += 8) {
        {   // As[kc][mn] = X[(c0+kc)*N + n0+mn]  (coalesced)
            int kc = t >> 5, mn = (t & 31) << 2;
            float4 v = *(const float4*)(Xb + (size_t)(c0 + kc) * NN + n0 + mn);
            *(float4*)(&As[kc][mn]) = v;
        }
        {   // Bs[kc][dn] = W[(d0+dn)*C + c0+kc]  (transpose on store)
            int dn = t >> 1, kc = (t & 1) << 2;
            float4 v = *(const float4*)(W + (size_t)(d0 + dn) * CC + c0 + kc);
            Bs[kc + 0][dn] = v.x; Bs[kc + 1][dn] = v.y;
            Bs[kc + 2][dn] = v.z; Bs[kc + 3][dn] = v.w;
        }
        __syncthreads();
#pragma unroll
        for (int kk = 0; kk < 8; ++kk) {
            float a[8], bv[8];
            *(float4*)(a)      = *(const float4*)(&As[kk][ty * 4]);
            *(float4*)(a + 4)  = *(const float4*)(&As[kk][64 + ty * 4]);
            *(float4*)(bv)     = *(const float4*)(&Bs[kk][tx * 4]);
            *(float4*)(bv + 4) = *(const float4*)(&Bs[kk][64 + tx * 4]);
#pragma unroll
            for (int i = 0; i < 8; i++)
#pragma unroll
                for (int j = 0; j < 8; j++)
                    acc[i][j] = fmaf(a[i], bv[j], acc[i][j]);
        }
        __syncthreads();
    }
#pragma unroll
    for (int ih = 0; ih < 2; ih++)
#pragma unroll
        for (int i = 0; i < 4; i++) {
            int r = n0 + ih * 64 + ty * 4 + i;
#pragma unroll
            for (int jh = 0; jh < 2; jh++) {
                int cb = d0 + jh * 64 + tx * 4;
                float4 v = make_float4(acc[ih*4+i][jh*4+0], acc[ih*4+i][jh*4+1],
                                       acc[ih*4+i][jh*4+2], acc[ih*4+i][jh*4+3]);
                *(float4*)(Yb + (size_t)r * Dout + cb) = v;
            }
        }
}

// =============================================================================
// qk: S[b,n,m] = SCALE * sum_d Q[b,n,d] * K[b,m,d]   (NT gemm)
// =============================================================================
__global__ __launch_bounds__(256)
void qk_kernel(int dir) {
    const int b  = blockIdx.z;
    const int n0 = blockIdx.x * 128;
    const int m0 = blockIdx.y * 128;
    const float* Qb = g_q[dir] + (size_t)b * NN * DD;
    const float* Kb = g_k[dir] + (size_t)b * NN * DD;
    float* Sb = g_p + ((size_t)dir * BB + b) * NN * NN;

    __shared__ float As[8][PAD];
    __shared__ float Bs[8][PAD];
    float acc[8][8] = {};
    const int t  = threadIdx.x;
    const int tx = t & 15, ty = t >> 4;

    for (int d0 = 0; d0 < DD; d0 += 8) {
        {   // As[kc][mn] = Q[(n0+mn)*D + d0+kc]  (transpose on store)
            int mn = t >> 1, kc = (t & 1) << 2;
            float4 v = *(const float4*)(Qb + (size_t)(n0 + mn) * DD + d0 + kc);
            As[kc + 0][mn] = v.x; As[kc + 1][mn] = v.y;
            As[kc + 2][mn] = v.z; As[kc + 3][mn] = v.w;
        }
        {   // Bs[kc][nn] = K[(m0+nn)*D + d0+kc]
            int nn = t >> 1, kc = (t & 1) << 2;
            float4 v = *(const float4*)(Kb + (size_t)(m0 + nn) * DD + d0 + kc);
            Bs[kc + 0][nn] = v.x; Bs[kc + 1][nn] = v.y;
            Bs[kc + 2][nn] = v.z; Bs[kc + 3][nn] = v.w;
        }
        __syncthreads();
#pragma unroll
        for (int kk = 0; kk < 8; ++kk) {
            float a[8], bv[8];
            *(float4*)(a)      = *(const float4*)(&As[kk][ty * 4]);
            *(float4*)(a + 4)  = *(const float4*)(&As[kk][64 + ty * 4]);
            *(float4*)(bv)     = *(const float4*)(&Bs[kk][tx * 4]);
            *(float4*)(bv + 4) = *(const float4*)(&Bs[kk][64 + tx * 4]);
#pragma unroll
            for (int i = 0; i < 8; i++)
#pragma unroll
                for (int j = 0; j < 8; j++)
                    acc[i][j] = fmaf(a[i], bv[j], acc[i][j]);
        }
        __syncthreads();
    }
#pragma unroll
    for (int ih = 0; ih < 2; ih++)
#pragma unroll
        for (int i = 0; i < 4; i++) {
            int r = n0 + ih * 64 + ty * 4 + i;
#pragma unroll
            for (int jh = 0; jh < 2; jh++) {
                int cb = m0 + jh * 64 + tx * 4;
                float4 v = make_float4(acc[ih*4+i][jh*4+0] * SCALE,
                                       acc[ih*4+i][jh*4+1] * SCALE,
                                       acc[ih*4+i][jh*4+2] * SCALE,
                                       acc[ih*4+i][jh*4+3] * SCALE);
                *(float4*)(Sb + (size_t)r * NN + cb) = v;
            }
        }
}

// =============================================================================
// softmax over rows of g_p (65536 rows of 1024)
// =============================================================================
__global__ void softmax_kernel() {
    __shared__ float red[8];
    const size_t row = blockIdx.x;
    float4* p = (float4*)(g_p + row * NN);
    const int t = threadIdx.x;

    float4 v = p[t];
    float m = fmaxf(fmaxf(v.x, v.y), fmaxf(v.z, v.w));
#pragma unroll
    for (int o = 16; o; o >>= 1) m = fmaxf(m, __shfl_xor_sync(0xffffffffu, m, o));
    if ((t & 31) == 0) red[t >> 5] = m;
    __syncthreads();
    m = red[0];
#pragma unroll
    for (int i = 1; i < 8; i++) m = fmaxf(m, red[i]);

    float e0 = expf(v.x - m), e1 = expf(v.y - m);
    float e2 = expf(v.z - m), e3 = expf(v.w - m);
    float s = e0 + e1 + e2 + e3;
#pragma unroll
    for (int o = 16; o; o >>= 1) s += __shfl_xor_sync(0xffffffffu, s, o);
    __syncthreads();
    if ((t & 31) == 0) red[t >> 5] = s;
    __syncthreads();
    s = red[0];
#pragma unroll
    for (int i = 1; i < 8; i++) s += red[i];
    float inv = 1.0f / s;
    p[t] = make_float4(e0 * inv, e1 * inv, e2 * inv, e3 * inv);
}

// =============================================================================
// pv: O[b,n,c] = sum_m P[b,n,m] * V[b,m,c]   (NN gemm)
// =============================================================================
__global__ __launch_bounds__(256)
void pv_kernel(int dir) {
    const int b  = blockIdx.z;
    const int n0 = blockIdx.x * 128;
    const int c0 = blockIdx.y * 128;
    const float* Pb = g_p + ((size_t)dir * BB + b) * NN * NN;
    const float* Vb = g_v[dir] + (size_t)b * NN * CC;
    float* Ob = g_o[dir] + (size_t)b * NN * CC;

    __shared__ float As[8][PAD];
    __shared__ float Bs[8][PAD];
    float acc[8][8] = {};
    const int t  = threadIdx.x;
    const int tx = t & 15, ty = t >> 4;

    for (int m0 = 0; m0 < NN; m0 += 8) {
        {   // As[kc][mn] = P[(n0+mn)*N + m0+kc]  (transpose on store)
            int mn = t >> 1, kc = (t & 1) << 2;
            float4 v = *(const float4*)(Pb + (size_t)(n0 + mn) * NN + m0 + kc);
            As[kc + 0][mn] = v.x; As[kc + 1][mn] = v.y;
            As[kc + 2][mn] = v.z; As[kc + 3][mn] = v.w;
        }
        {   // Bs[kc][cn] = V[(m0+kc)*C + c0+cn]  (coalesced)
            int kc = t >> 5, cn = (t & 31) << 2;
            float4 v = *(const float4*)(Vb + (size_t)(m0 + kc) * CC + c0 + cn);
            *(float4*)(&Bs[kc][cn]) = v;
        }
        __syncthreads();
#pragma unroll
        for (int kk = 0; kk < 8; ++kk) {
            float a[8], bv[8];
            *(float4*)(a)      = *(const float4*)(&As[kk][ty * 4]);
            *(float4*)(a + 4)  = *(const float4*)(&As[kk][64 + ty * 4]);
            *(float4*)(bv)     = *(const float4*)(&Bs[kk][tx * 4]);
            *(float4*)(bv + 4) = *(const float4*)(&Bs[kk][64 + tx * 4]);
#pragma unroll
            for (int i = 0; i < 8; i++)
#pragma unroll
                for (int j = 0; j < 8; j++)
                    acc[i][j] = fmaf(a[i], bv[j], acc[i][j]);
        }
        __syncthreads();
    }
#pragma unroll
    for (int ih = 0; ih < 2; ih++)
#pragma unroll
        for (int i = 0; i < 4; i++) {
            int r = n0 + ih * 64 + ty * 4 + i;
#pragma unroll
            for (int jh = 0; jh < 2; jh++) {
                int cb = c0 + jh * 64 + tx * 4;
                float4 v = make_float4(acc[ih*4+i][jh*4+0], acc[ih*4+i][jh*4+1],
                                       acc[ih*4+i][jh*4+2], acc[ih*4+i][jh*4+3]);
                *(float4*)(Ob + (size_t)r * CC + cb) = v;
            }
        }
}

// =============================================================================
// fuse: out[b,c,n] = relu( sum_{k<256} fw[c,k] f[b,k,n]
//                        + sum_{k<256} fw[c,256+k] att[b,n,k] + fb[c] ) + f[b,c,n]
// writes pre-LN result into d_out half "dir"
// =============================================================================
__global__ __launch_bounds__(256)
void fuse_kernel(const float* __restrict__ f, const float* __restrict__ fw,
                 const float* __restrict__ fbias, int dir, float* __restrict__ outp) {
    const int b  = blockIdx.z;
    const int n0 = blockIdx.x * 128;
    const int c0 = blockIdx.y * 128;
    const float* fb = f + (size_t)b * CC * NN;
    const float* attb = g_o[dir] + (size_t)b * NN * CC;
    float* ob = outp + ((size_t)dir * BB + b) * CC * NN;

    __shared__ float As[8][PAD];
    __shared__ float Bs[8][PAD];
    float acc[8][8] = {};
    const int t  = threadIdx.x;
    const int tx = t & 15, ty = t >> 4;

    for (int k0 = 0; k0 < 2 * CC; k0 += 8) {
        if (k0 < CC) {  // feature part: column-major wrt k -> direct coalesced
            int kc = t >> 5, mn = (t & 31) << 2;
            float4 v = *(const float4*)(fb + (size_t)(k0 + kc) * NN + n0 + mn);
            *(float4*)(&As[kc][mn]) = v;
        } else {        // attention part: row-major -> transpose on store
            int mn = t >> 1, kc = (t & 1) << 2;
            float4 v = *(const float4*)(attb + (size_t)(n0 + mn) * CC + (k0 - CC) + kc);
            As[kc + 0][mn] = v.x; As[kc + 1][mn] = v.y;
            As[kc + 2][mn] = v.z; As[kc + 3][mn] = v.w;
        }
        {   // Bs[kc][cn] = fw[(c0+cn)*512 + k0+kc]
            int cn = t >> 1, kc = (t & 1) << 2;
            float4 v = *(const float4*)(fw + (size_t)(c0 + cn) * (2 * CC) + k0 + kc);
            Bs[kc + 0][cn] = v.x; Bs[kc + 1][cn] = v.y;
            Bs[kc + 2][cn] = v.z; Bs[kc + 3][cn] = v.w;
        }
        __syncthreads();
#pragma unroll
        for (int kk = 0; kk < 8; ++kk) {
            float a[8], bv[8];
            *(float4*)(a)      = *(const float4*)(&As[kk][ty * 4]);
            *(float4*)(a + 4)  = *(const float4*)(&As[kk][64 + ty * 4]);
            *(float4*)(bv)     = *(const float4*)(&Bs[kk][tx * 4]);
            *(float4*)(bv + 4) = *(const float4*)(&Bs[kk][64 + tx * 4]);
#pragma unroll
            for (int i = 0; i < 8; i++)
#pragma unroll
                for (int j = 0; j < 8; j++)
                    acc[i][j] = fmaf(a[i], bv[j], acc[i][j]);
        }
        __syncthreads();
    }
    // epilogue: bias + relu + residual, store transposed (c, n)
#pragma unroll
    for (int jh = 0; jh < 2; jh++)
#pragma unroll
        for (int j = 0; j < 4; j++) {
            int c = c0 + jh * 64 + tx * 4 + j;
            float bias = fbias[c];
#pragma unroll
            for (int ih = 0; ih < 2; ih++) {
                int np = n0 + ih * 64 + ty * 4;
                float4 res = *(const float4*)(fb + (size_t)c * NN + np);
                float4 r;
                r.x = fmaxf(acc[ih*4+0][jh*4+j] + bias, 0.f) + res.x;
                r.y = fmaxf(acc[ih*4+1][jh*4+j] + bias, 0.f) + res.y;
                r.z = fmaxf(acc[ih*4+2][jh*4+j] + bias, 0.f) + res.z;
                r.w = fmaxf(acc[ih*4+3][jh*4+j] + bias, 0.f) + res.w;
                *(float4*)(ob + (size_t)c * NN + np) = r;
            }
        }
}

// =============================================================================
// layernorm: per (dir,b) reduce over C*N, then normalize in place
// =============================================================================
__global__ void ln_reduce_kernel(const float* __restrict__ outp) {
    __shared__ float rs[8], rss[8];
    const int seg = blockIdx.x;  // dir*32 + b
    const float4* p = (const float4*)(outp + (size_t)seg * CC * NN);
    const int t = threadIdx.x;
    float s = 0.f, ss = 0.f;
    for (int i = t; i < CC * NN / 4; i += 256) {
        float4 v = p[i];
        s  += v.x + v.y + v.z + v.w;
        ss += v.x * v.x + v.y * v.y + v.z * v.z + v.w * v.w;
    }
#pragma unroll
    for (int o = 16; o; o >>= 1) {
        s  += __shfl_xor_sync(0xffffffffu, s, o);
        ss += __shfl_xor_sync(0xffffffffu, ss, o);
    }
    if ((t & 31) == 0) { rs[t >> 5] = s; rss[t >> 5] = ss; }
    __syncthreads();
    if (t == 0) {
        float ts = 0.f, tss = 0.f;
#pragma unroll
        for (int i = 0; i < 8; i++) { ts += rs[i]; tss += rss[i]; }
        float inv_n = 1.0f / (CC * NN);
        float mean = ts * inv_n;
        float var  = tss * inv_n - mean * mean;
        g_red[seg * 2 + 0] = mean;
        g_red[seg * 2 + 1] = rsqrtf(var + EPS);
    }
}

__global__ void ln_norm_kernel(float* __restrict__ outp,
                               const float* __restrict__ lnw_s, const float* __restrict__ lnb_s,
                               const float* __restrict__ lnw_i, const float* __restrict__ lnb_i) {
    const int total4 = 2 * BB * CC * NN / 4;
    for (int i = blockIdx.x * blockDim.x + threadIdx.x; i < total4;
         i += gridDim.x * blockDim.x) {
        int flat = i * 4;
        int seg = flat / (CC * NN);
        int c = (flat >> 10) & (CC - 1);
        float mean = g_red[seg * 2 + 0];
        float rstd = g_red[seg * 2 + 1];
        bool isI = seg >= BB;
        float w  = (isI ? lnw_i : lnw_s)[c];
        float bi = (isI ? lnb_i : lnb_s)[c];
        float4 v = ((float4*)outp)[i];
        v.x = (v.x - mean) * rstd * w + bi;
        v.y = (v.y - mean) * rstd * w + bi;
        v.z = (v.z - mean) * rstd * w + bi;
        v.w = (v.w - mean) * rstd * w + bi;
        ((float4*)outp)[i] = v;
    }
}

// =============================================================================
extern "C" void kernel_launch(void* const* d_in, const int* in_sizes, int n_in,
                              void* d_out, int out_size) {
    const float* fs     = (const float*)d_in[0];
    const float* fi     = (const float*)d_in[1];
    const float* qs_w   = (const float*)d_in[2];
    const float* ks_w   = (const float*)d_in[3];
    const float* vs_w   = (const float*)d_in[4];
    const float* qi_w   = (const float*)d_in[5];
    const float* ki_w   = (const float*)d_in[6];
    const float* vi_w   = (const float*)d_in[7];
    const float* fuse_w = (const float*)d_in[8];
    const float* fuse_b = (const float*)d_in[9];
    const float* ln_s_w = (const float*)d_in[10];
    const float* ln_s_b = (const float*)d_in[11];
    const float* ln_i_w = (const float*)d_in[12];
    const float* ln_i_b = (const float*)d_in[13];
    float* out = (float*)d_out;

    dim3 thr(256);
    // dir 0 -> fs_out branch: attn = attend(q=fi@qi_w, k=fs@ks_w, v=fs@vs_w)
    proj_kernel<<<dim3(8, 1, BB), thr>>>(fi, qi_w, 0, 0);
    proj_kernel<<<dim3(8, 1, BB), thr>>>(fs, ks_w, 0, 1);
    proj_kernel<<<dim3(8, 2, BB), thr>>>(fs, vs_w, 0, 2);
    // dir 1 -> fi_out branch: attn = attend(q=fs@qs_w, k=fi@ki_w, v=fi@vi_w)
    proj_kernel<<<dim3(8, 1, BB), thr>>>(fs, qs_w, 1, 0);
    proj_kernel<<<dim3(8, 1, BB), thr>>>(fi, ki_w, 1, 1);
    proj_kernel<<<dim3(8, 2, BB), thr>>>(fi, vi_w, 1, 2);

    qk_kernel<<<dim3(8, 8, BB), thr>>>(0);
    qk_kernel<<<dim3(8, 8, BB), thr>>>(1);

    softmax_kernel<<<2 * BB * NN, 256>>>();

    pv_kernel<<<dim3(8, 2, BB), thr>>>(0);
    pv_kernel<<<dim3(8, 2, BB), thr>>>(1);

    fuse_kernel<<<dim3(8, 2, BB), thr>>>(fs, fuse_w, fuse_b, 0, out);
    fuse_kernel<<<dim3(8, 2, BB), thr>>>(fi, fuse_w, fuse_b, 1, out);

    ln_reduce_kernel<<<64, 256>>>(out);
    ln_norm_kernel<<<4096, 256>>>(out, ln_s_w, ln_s_b, ln_i_w, ln_i_b);
}

// round 4
// speedup vs baseline: 2.2149x; 2.2149x over previous
#include <cuda_runtime.h>
#include <math.h>

#define BB 32
#define CC 256
#define DD 128
#define NN 1024
#define EPS 1e-5f
#define SCALE 0.08838834764831843f  // 1/sqrt(128)

#define PADK 136   // smem row stride; PADK % 32 == 8 -> conflict-free fragment LDS

// ---------------- scratch (device globals; no allocations allowed) ----------
__device__ float g_q[2][BB * NN * DD];
__device__ float g_k[2][BB * NN * DD];
__device__ float g_v[2][BB * NN * CC];
__device__ float g_o[2][BB * NN * CC];
__device__ float g_p[2ll * BB * NN * NN];
__device__ float g_red[64 * 2];

// ---------------- tf32 helpers ----------------------------------------------
__device__ __forceinline__ unsigned f2tf(float f) {
    unsigned u;
    asm("cvt.rna.tf32.f32 %0, %1;" : "=r"(u) : "f"(f));
    return u;
}

__device__ __forceinline__ void mma8(float* c, const unsigned* a, const unsigned* b) {
    asm volatile(
        "mma.sync.aligned.m16n8k8.row.col.f32.tf32.tf32.f32 "
        "{%0,%1,%2,%3}, {%4,%5,%6,%7}, {%8,%9}, {%0,%1,%2,%3};"
        : "+f"(c[0]), "+f"(c[1]), "+f"(c[2]), "+f"(c[3])
        : "r"(a[0]), "r"(a[1]), "r"(a[2]), "r"(a[3]), "r"(b[0]), "r"(b[1]));
}

// ---------------- smem tile loaders ------------------------------------------
// direct: S[k][x] = src[(k0+k)*ld + x0+x]   (16 x 128 tile)
__device__ __forceinline__ void ldg_direct(float4 v[2], const float* __restrict__ src,
                                           int ld, int k0, int x0, int t) {
    int row = t >> 4, col = (t & 15) * 4;
    const float* p = src + (size_t)(k0 + row) * ld + x0 + col;
    v[0] = *(const float4*)(p);
    v[1] = *(const float4*)(p + 64);
}
__device__ __forceinline__ void sts_direct(unsigned (*S)[PADK], const float4 v[2], int t) {
    int row = t >> 4, col = (t & 15) * 4;
    uint4 u0 = make_uint4(f2tf(v[0].x), f2tf(v[0].y), f2tf(v[0].z), f2tf(v[0].w));
    uint4 u1 = make_uint4(f2tf(v[1].x), f2tf(v[1].y), f2tf(v[1].z), f2tf(v[1].w));
    *(uint4*)&S[row][col]      = u0;
    *(uint4*)&S[row][col + 64] = u1;
}
// transpose: S[k][x] = src[(x0+x)*ld + k0+k]
__device__ __forceinline__ void ldg_trans(float4 v[2], const float* __restrict__ src,
                                          int ld, int k0, int x0, int t) {
    int x = t >> 1, k4 = (t & 1) * 4;
    const float* p = src + (size_t)(x0 + x) * ld + k0 + k4;
    v[0] = *(const float4*)(p);
    v[1] = *(const float4*)(p + 8);
}
__device__ __forceinline__ void sts_trans(unsigned (*S)[PADK], const float4 v[2], int t) {
    int x = t >> 1, k4 = (t & 1) * 4;
    S[k4 + 0][x] = f2tf(v[0].x); S[k4 + 1][x]  = f2tf(v[0].y);
    S[k4 + 2][x] = f2tf(v[0].z); S[k4 + 3][x]  = f2tf(v[0].w);
    S[k4 + 8][x] = f2tf(v[1].x); S[k4 + 9][x]  = f2tf(v[1].y);
    S[k4 +10][x] = f2tf(v[1].z); S[k4 +11][x]  = f2tf(v[1].w);
}

// ---------------- warp-MMA compute on one (16 x 128)x(16 x 128) smem tile ----
__device__ __forceinline__ void compute_tile(const unsigned (*As)[PADK],
                                             const unsigned (*Bs)[PADK],
                                             float acc[4][4][4],
                                             int wm, int wn, int lane) {
    const int r = lane >> 2, cq = lane & 3;
#pragma unroll
    for (int kk = 0; kk < 16; kk += 8) {
        unsigned af[4][4], bf[4][2];
#pragma unroll
        for (int mt = 0; mt < 4; mt++) {
            int mb = wm * 64 + mt * 16;
            af[mt][0] = As[kk + cq][mb + r];
            af[mt][1] = As[kk + cq][mb + r + 8];
            af[mt][2] = As[kk + cq + 4][mb + r];
            af[mt][3] = As[kk + cq + 4][mb + r + 8];
        }
#pragma unroll
        for (int nt = 0; nt < 4; nt++) {
            int nb = wn * 32 + nt * 8;
            bf[nt][0] = Bs[kk + cq][nb + r];
            bf[nt][1] = Bs[kk + cq + 4][nb + r];
        }
#pragma unroll
        for (int mt = 0; mt < 4; mt++)
#pragma unroll
            for (int nt = 0; nt < 4; nt++)
                mma8(acc[mt][nt], af[mt], bf[nt]);
    }
}

// =============================================================================
// proj: Y[b,n,d] = sum_c X[b,c,n] * W[d,c]
// =============================================================================
__global__ __launch_bounds__(256, 2)
void proj_kernel(const float* __restrict__ X, const float* __restrict__ W,
                 int dir, int which) {
    float* Y; int Dout;
    if (which == 0)      { Y = g_q[dir]; Dout = DD; }
    else if (which == 1) { Y = g_k[dir]; Dout = DD; }
    else                 { Y = g_v[dir]; Dout = CC; }

    __shared__ unsigned As[2][16][PADK], Bs[2][16][PADK];
    const int b = blockIdx.z, n0 = blockIdx.x * 128, d0 = blockIdx.y * 128;
    const float* Xb = X + (size_t)b * CC * NN;
    float* Yb = Y + (size_t)b * NN * Dout;
    const int t = threadIdx.x, lane = t & 31, w = t >> 5;
    const int wm = w >> 2, wn = w & 3;
    float acc[4][4][4] = {};
    float4 va[2], vb[2];

    ldg_direct(va, Xb, NN, 0, n0, t);
    ldg_trans (vb, W,  CC, 0, d0, t);
    sts_direct(As[0], va, t); sts_trans(Bs[0], vb, t);
    __syncthreads();
    const int NIT = CC / 16;
    for (int it = 0; it < NIT; it++) {
        int buf = it & 1;
        if (it + 1 < NIT) {
            ldg_direct(va, Xb, NN, (it + 1) * 16, n0, t);
            ldg_trans (vb, W,  CC, (it + 1) * 16, d0, t);
        }
        compute_tile(As[buf], Bs[buf], acc, wm, wn, lane);
        if (it + 1 < NIT) {
            sts_direct(As[buf ^ 1], va, t); sts_trans(Bs[buf ^ 1], vb, t);
            __syncthreads();
        }
    }
    const int r = lane >> 2, cq = lane & 3;
#pragma unroll
    for (int mt = 0; mt < 4; mt++) {
        int row = n0 + wm * 64 + mt * 16 + r;
#pragma unroll
        for (int nt = 0; nt < 4; nt++) {
            int col = d0 + wn * 32 + nt * 8 + cq * 2;
            *(float2*)(Yb + (size_t)row * Dout + col) =
                make_float2(acc[mt][nt][0], acc[mt][nt][1]);
            *(float2*)(Yb + (size_t)(row + 8) * Dout + col) =
                make_float2(acc[mt][nt][2], acc[mt][nt][3]);
        }
    }
}

// =============================================================================
// qk: S[z,n,m] = SCALE * sum_d Q[n,d] * K[m,d]
// =============================================================================
__global__ __launch_bounds__(256, 2)
void qk_kernel() {
    __shared__ unsigned As[2][16][PADK], Bs[2][16][PADK];
    const int z = blockIdx.z, dir = z >> 5, b = z & 31;
    const int n0 = blockIdx.x * 128, m0 = blockIdx.y * 128;
    const float* Qb = g_q[dir] + (size_t)b * NN * DD;
    const float* Kb = g_k[dir] + (size_t)b * NN * DD;
    float* Sb = g_p + (size_t)z * NN * NN;
    const int t = threadIdx.x, lane = t & 31, w = t >> 5;
    const int wm = w >> 2, wn = w & 3;
    float acc[4][4][4] = {};
    float4 va[2], vb[2];

    ldg_trans(va, Qb, DD, 0, n0, t);
    ldg_trans(vb, Kb, DD, 0, m0, t);
    sts_trans(As[0], va, t); sts_trans(Bs[0], vb, t);
    __syncthreads();
    const int NIT = DD / 16;
    for (int it = 0; it < NIT; it++) {
        int buf = it & 1;
        if (it + 1 < NIT) {
            ldg_trans(va, Qb, DD, (it + 1) * 16, n0, t);
            ldg_trans(vb, Kb, DD, (it + 1) * 16, m0, t);
        }
        compute_tile(As[buf], Bs[buf], acc, wm, wn, lane);
        if (it + 1 < NIT) {
            sts_trans(As[buf ^ 1], va, t); sts_trans(Bs[buf ^ 1], vb, t);
            __syncthreads();
        }
    }
    const int r = lane >> 2, cq = lane & 3;
#pragma unroll
    for (int mt = 0; mt < 4; mt++) {
        int row = n0 + wm * 64 + mt * 16 + r;
#pragma unroll
        for (int nt = 0; nt < 4; nt++) {
            int col = m0 + wn * 32 + nt * 8 + cq * 2;
            *(float2*)(Sb + (size_t)row * NN + col) =
                make_float2(acc[mt][nt][0] * SCALE, acc[mt][nt][1] * SCALE);
            *(float2*)(Sb + (size_t)(row + 8) * NN + col) =
                make_float2(acc[mt][nt][2] * SCALE, acc[mt][nt][3] * SCALE);
        }
    }
}

// =============================================================================
// softmax over rows of g_p (65536 rows of 1024)
// =============================================================================
__global__ void softmax_kernel() {
    __shared__ float red[8];
    const size_t row = blockIdx.x;
    float4* p = (float4*)(g_p + row * NN);
    const int t = threadIdx.x;

    float4 v = p[t];
    float m = fmaxf(fmaxf(v.x, v.y), fmaxf(v.z, v.w));
#pragma unroll
    for (int o = 16; o; o >>= 1) m = fmaxf(m, __shfl_xor_sync(0xffffffffu, m, o));
    if ((t & 31) == 0) red[t >> 5] = m;
    __syncthreads();
    m = red[0];
#pragma unroll
    for (int i = 1; i < 8; i++) m = fmaxf(m, red[i]);

    float e0 = expf(v.x - m), e1 = expf(v.y - m);
    float e2 = expf(v.z - m), e3 = expf(v.w - m);
    float s = e0 + e1 + e2 + e3;
#pragma unroll
    for (int o = 16; o; o >>= 1) s += __shfl_xor_sync(0xffffffffu, s, o);
    __syncthreads();
    if ((t & 31) == 0) red[t >> 5] = s;
    __syncthreads();
    s = red[0];
#pragma unroll
    for (int i = 1; i < 8; i++) s += red[i];
    float inv = 1.0f / s;
    p[t] = make_float4(e0 * inv, e1 * inv, e2 * inv, e3 * inv);
}

// =============================================================================
// pv: O[n,c] = sum_m P[n,m] * V[m,c]
// =============================================================================
__global__ __launch_bounds__(256, 2)
void pv_kernel() {
    __shared__ unsigned As[2][16][PADK], Bs[2][16][PADK];
    const int z = blockIdx.z, dir = z >> 5, b = z & 31;
    const int n0 = blockIdx.x * 128, c0 = blockIdx.y * 128;
    const float* Pb = g_p + (size_t)z * NN * NN;
    const float* Vb = g_v[dir] + (size_t)b * NN * CC;
    float* Ob = g_o[dir] + (size_t)b * NN * CC;
    const int t = threadIdx.x, lane = t & 31, w = t >> 5;
    const int wm = w >> 2, wn = w & 3;
    float acc[4][4][4] = {};
    float4 va[2], vb4[2];

    ldg_trans (va,  Pb, NN, 0, n0, t);
    ldg_direct(vb4, Vb, CC, 0, c0, t);
    sts_trans(As[0], va, t); sts_direct(Bs[0], vb4, t);
    __syncthreads();
    const int NIT = NN / 16;
    for (int it = 0; it < NIT; it++) {
        int buf = it & 1;
        if (it + 1 < NIT) {
            ldg_trans (va,  Pb, NN, (it + 1) * 16, n0, t);
            ldg_direct(vb4, Vb, CC, (it + 1) * 16, c0, t);
        }
        compute_tile(As[buf], Bs[buf], acc, wm, wn, lane);
        if (it + 1 < NIT) {
            sts_trans(As[buf ^ 1], va, t); sts_direct(Bs[buf ^ 1], vb4, t);
            __syncthreads();
        }
    }
    const int r = lane >> 2, cq = lane & 3;
#pragma unroll
    for (int mt = 0; mt < 4; mt++) {
        int row = n0 + wm * 64 + mt * 16 + r;
#pragma unroll
        for (int nt = 0; nt < 4; nt++) {
            int col = c0 + wn * 32 + nt * 8 + cq * 2;
            *(float2*)(Ob + (size_t)row * CC + col) =
                make_float2(acc[mt][nt][0], acc[mt][nt][1]);
            *(float2*)(Ob + (size_t)(row + 8) * CC + col) =
                make_float2(acc[mt][nt][2], acc[mt][nt][3]);
        }
    }
}

// =============================================================================
// fuse (transposed: M = c, N = n):
// out[c,n] = relu( sum_k fw[c,k]*concat(f,att)[k,n] + fb[c] ) + f[c,n]
// =============================================================================
__global__ __launch_bounds__(256, 2)
void fuse_kernel(const float* __restrict__ fs, const float* __restrict__ fi,
                 const float* __restrict__ fw, const float* __restrict__ fbias,
                 float* __restrict__ outp) {
    __shared__ unsigned As[2][16][PADK], Bs[2][16][PADK];
    const int z = blockIdx.z, dir = z >> 5, b = z & 31;
    const int n0 = blockIdx.x * 128, c0 = blockIdx.y * 128;
    const float* f = dir ? fi : fs;
    const float* fb = f + (size_t)b * CC * NN;
    const float* attb = g_o[dir] + (size_t)b * NN * CC;
    float* ob = outp + (size_t)z * CC * NN;
    const int t = threadIdx.x, lane = t & 31, w = t >> 5;
    const int wm = w >> 2, wn = w & 3;
    float acc[4][4][4] = {};
    float4 va[2], vb4[2];

    ldg_trans (va,  fw, 2 * CC, 0, c0, t);
    ldg_direct(vb4, fb, NN,     0, n0, t);
    sts_trans(As[0], va, t); sts_direct(Bs[0], vb4, t);
    __syncthreads();
    const int NIT = (2 * CC) / 16;
    for (int it = 0; it < NIT; it++) {
        int buf = it & 1;
        bool nxt_direct = false;
        if (it + 1 < NIT) {
            int k0 = (it + 1) * 16;
            ldg_trans(va, fw, 2 * CC, k0, c0, t);
            nxt_direct = (k0 < CC);
            if (nxt_direct) ldg_direct(vb4, fb,   NN, k0,      n0, t);
            else            ldg_trans (vb4, attb, CC, k0 - CC, n0, t);
        }
        compute_tile(As[buf], Bs[buf], acc, wm, wn, lane);
        if (it + 1 < NIT) {
            sts_trans(As[buf ^ 1], va, t);
            if (nxt_direct) sts_direct(Bs[buf ^ 1], vb4, t);
            else            sts_trans (Bs[buf ^ 1], vb4, t);
            __syncthreads();
        }
    }
    const int r = lane >> 2, cq = lane & 3;
#pragma unroll
    for (int mt = 0; mt < 4; mt++) {
        int crow = c0 + wm * 64 + mt * 16 + r;
        float b0 = fbias[crow], b1 = fbias[crow + 8];
#pragma unroll
        for (int nt = 0; nt < 4; nt++) {
            int ncol = n0 + wn * 32 + nt * 8 + cq * 2;
            float2 r0 = *(const float2*)(fb + (size_t)crow * NN + ncol);
            float2 r1 = *(const float2*)(fb + (size_t)(crow + 8) * NN + ncol);
            float2 o0, o1;
            o0.x = fmaxf(acc[mt][nt][0] + b0, 0.f) + r0.x;
            o0.y = fmaxf(acc[mt][nt][1] + b0, 0.f) + r0.y;
            o1.x = fmaxf(acc[mt][nt][2] + b1, 0.f) + r1.x;
            o1.y = fmaxf(acc[mt][nt][3] + b1, 0.f) + r1.y;
            *(float2*)(ob + (size_t)crow * NN + ncol)       = o0;
            *(float2*)(ob + (size_t)(crow + 8) * NN + ncol) = o1;
        }
    }
}

// =============================================================================
// layernorm: per (dir,b) reduce over C*N, then normalize in place
// =============================================================================
__global__ void ln_reduce_kernel(const float* __restrict__ outp) {
    __shared__ float rs[8], rss[8];
    const int seg = blockIdx.x;
    const float4* p = (const float4*)(outp + (size_t)seg * CC * NN);
    const int t = threadIdx.x;
    float s = 0.f, ss = 0.f;
    for (int i = t; i < CC * NN / 4; i += 256) {
        float4 v = p[i];
        s  += v.x + v.y + v.z + v.w;
        ss += v.x * v.x + v.y * v.y + v.z * v.z + v.w * v.w;
    }
#pragma unroll
    for (int o = 16; o; o >>= 1) {
        s  += __shfl_xor_sync(0xffffffffu, s, o);
        ss += __shfl_xor_sync(0xffffffffu, ss, o);
    }
    if ((t & 31) == 0) { rs[t >> 5] = s; rss[t >> 5] = ss; }
    __syncthreads();
    if (t == 0) {
        float ts = 0.f, tss = 0.f;
#pragma unroll
        for (int i = 0; i < 8; i++) { ts += rs[i]; tss += rss[i]; }
        float inv_n = 1.0f / (CC * NN);
        float mean = ts * inv_n;
        float var  = tss * inv_n - mean * mean;
        g_red[seg * 2 + 0] = mean;
        g_red[seg * 2 + 1] = rsqrtf(var + EPS);
    }
}

__global__ void ln_norm_kernel(float* __restrict__ outp,
                               const float* __restrict__ lnw_s, const float* __restrict__ lnb_s,
                               const float* __restrict__ lnw_i, const float* __restrict__ lnb_i) {
    const int total4 = 2 * BB * CC * NN / 4;
    for (int i = blockIdx.x * blockDim.x + threadIdx.x; i < total4;
         i += gridDim.x * blockDim.x) {
        int flat = i * 4;
        int seg = flat / (CC * NN);
        int c = (flat >> 10) & (CC - 1);
        float mean = g_red[seg * 2 + 0];
        float rstd = g_red[seg * 2 + 1];
        bool isI = seg >= BB;
        float w  = (isI ? lnw_i : lnw_s)[c];
        float bi = (isI ? lnb_i : lnb_s)[c];
        float4 v = ((float4*)outp)[i];
        v.x = (v.x - mean) * rstd * w + bi;
        v.y = (v.y - mean) * rstd * w + bi;
        v.z = (v.z - mean) * rstd * w + bi;
        v.w = (v.w - mean) * rstd * w + bi;
        ((float4*)outp)[i] = v;
    }
}

// =============================================================================
extern "C" void kernel_launch(void* const* d_in, const int* in_sizes, int n_in,
                              void* d_out, int out_size) {
    const float* fs     = (const float*)d_in[0];
    const float* fi     = (const float*)d_in[1];
    const float* qs_w   = (const float*)d_in[2];
    const float* ks_w   = (const float*)d_in[3];
    const float* vs_w   = (const float*)d_in[4];
    const float* qi_w   = (const float*)d_in[5];
    const float* ki_w   = (const float*)d_in[6];
    const float* vi_w   = (const float*)d_in[7];
    const float* fuse_w = (const float*)d_in[8];
    const float* fuse_b = (const float*)d_in[9];
    const float* ln_s_w = (const float*)d_in[10];
    const float* ln_s_b = (const float*)d_in[11];
    const float* ln_i_w = (const float*)d_in[12];
    const float* ln_i_b = (const float*)d_in[13];
    float* out = (float*)d_out;

    dim3 thr(256);
    // dir 0 -> fs_out branch: attn = attend(q=fi@qi_w, k=fs@ks_w, v=fs@vs_w)
    proj_kernel<<<dim3(8, 1, BB), thr>>>(fi, qi_w, 0, 0);
    proj_kernel<<<dim3(8, 1, BB), thr>>>(fs, ks_w, 0, 1);
    proj_kernel<<<dim3(8, 2, BB), thr>>>(fs, vs_w, 0, 2);
    // dir 1 -> fi_out branch: attn = attend(q=fs@qs_w, k=fi@ki_w, v=fi@vi_w)
    proj_kernel<<<dim3(8, 1, BB), thr>>>(fs, qs_w, 1, 0);
    proj_kernel<<<dim3(8, 1, BB), thr>>>(fi, ki_w, 1, 1);
    proj_kernel<<<dim3(8, 2, BB), thr>>>(fi, vi_w, 1, 2);

    qk_kernel<<<dim3(8, 8, 64), thr>>>();

    softmax_kernel<<<2 * BB * NN, 256>>>();

    pv_kernel<<<dim3(8, 2, 64), thr>>>();

    fuse_kernel<<<dim3(8, 2, 64), thr>>>(fs, fi, fuse_w, fuse_b, out);

    ln_reduce_kernel<<<64, 256>>>(out);
    ln_norm_kernel<<<4096, 256>>>(out, ln_s_w, ln_s_b, ln_i_w, ln_i_b);
}